// round 11
// baseline (speedup 1.0000x reference)
#include <cuda_runtime.h>
#include <cuda_fp16.h>
#include <cstdint>

#define H   128
#define MH  256
#define NJ  2000
#define NJP 2048
#define NM  50
#define NS  200
#define G   8

#define PADK  264                 // padded row length for Pj/Pm/B (halves)
#define ROWB  528                 // bytes per padded row
#define PJK   136                 // padded row length for W1t / A-tiles (halves)
#define PJB   272                 // bytes

// ---------------- device scratch ----------------
__device__ __half d_Pj16[NJP * PADK];   // job projections, fp16
__device__ __half d_Pm16[NM * PADK];    // machine proj + cvec, fp16
__device__ __half d_B16[MH * PADK];     // aW2^T [n][k] fp16
__device__ __half d_W1t16[MH * PJK];    // aW1[0:128]^T [n][k] fp16
__device__ __half d_jemb16[NJ * H];     // job_emb fp16
__device__ float  d_partJ[128 * H];
__device__ float  d_partM[H];
__device__ float  d_partS[8 * H];

__device__ __forceinline__ float relu(float x) { return fmaxf(x, 0.f); }

__device__ __forceinline__ uint32_t smem_u32(const void* p) {
    uint32_t a;
    asm("{ .reg .u64 t; cvta.to.shared.u64 t, %1; cvt.u32.u64 %0, t; }" : "=r"(a) : "l"(p));
    return a;
}
__device__ __forceinline__ void ldm_x4(uint32_t& r0, uint32_t& r1, uint32_t& r2,
                                       uint32_t& r3, uint32_t addr) {
    asm volatile("ldmatrix.sync.aligned.m8n8.x4.shared.b16 {%0,%1,%2,%3}, [%4];"
                 : "=r"(r0), "=r"(r1), "=r"(r2), "=r"(r3) : "r"(addr));
}
__device__ __forceinline__ uint32_t addrelu2(uint32_t a, uint32_t pm) {
    const __half2 z = __float2half2_rn(0.f);
    __half2 x = __hadd2(*(__half2*)&a, *(__half2*)&pm);
    x = __hmax2(x, z);
    return *(uint32_t*)&x;
}
#define HMMA(acc, A0, A1, A2, A3, B0, B1)                                   \
    asm volatile(                                                            \
        "mma.sync.aligned.m16n8k16.row.col.f32.f16.f16.f32 "                \
        "{%0,%1,%2,%3}, {%4,%5,%6,%7}, {%8,%9}, {%0,%1,%2,%3};"             \
        : "+f"(acc[0]), "+f"(acc[1]), "+f"(acc[2]), "+f"(acc[3])            \
        : "r"(A0), "r"(A1), "r"(A2), "r"(A3), "r"(B0), "r"(B1))

// ===========================================================================
// k_prep: 333 blocks x 256.
//   0..31   : transpose aW1[0:128] -> d_W1t16
//   32..95  : transpose aW2       -> d_B16
//   96..223 : job partial sums (128 blocks, 4 DRAM rounds each)
//   224     : machine partial
//   225..232: setup partials (8)
//   233..332: convert job_emb -> d_jemb16 (20 rows/block)
// ===========================================================================
__global__ __launch_bounds__(256)
void k_prep(const float* __restrict__ job_emb,
            const float* __restrict__ machine_emb,
            const float* __restrict__ setup_emb,
            const float* __restrict__ aW1,
            const float* __restrict__ aW2)
{
    __shared__ float buf[32 * 33];
    const int bx = blockIdx.x;
    const int tid = threadIdx.x;

    if (bx < 32) {
        float (*tt)[33] = (float(*)[33])buf;
        const int t = bx;
        const int k0 = (t >> 3) * 32, n0 = (t & 7) * 32;
        const int r = tid >> 5, c = tid & 31;
        #pragma unroll
        for (int i = 0; i < 4; i++)
            tt[r + i * 8][c] = aW1[(k0 + r + i * 8) * MH + n0 + c];
        __syncthreads();
        #pragma unroll
        for (int i = 0; i < 4; i++)
            d_W1t16[(n0 + r + i * 8) * PJK + k0 + c] = __float2half_rn(tt[c][r + i * 8]);
    } else if (bx < 96) {
        float (*tt)[33] = (float(*)[33])buf;
        const int t = bx - 32;
        const int k0 = (t >> 3) * 32, n0 = (t & 7) * 32;
        const int r = tid >> 5, c = tid & 31;
        #pragma unroll
        for (int i = 0; i < 4; i++)
            tt[r + i * 8][c] = aW2[(k0 + r + i * 8) * MH + n0 + c];
        __syncthreads();
        #pragma unroll
        for (int i = 0; i < 4; i++)
            d_B16[(n0 + r + i * 8) * PADK + k0 + c] = __float2half_rn(tt[c][r + i * 8]);
    } else if (bx < 224) {
        if (tid >= 128) return;
        const int col = tid;
        const int pb = bx - 96;                 // 0..127
        float s0 = 0.f, s1 = 0.f, s2 = 0.f, s3 = 0.f;
        int r = pb;
        for (; r + 384 < NJ; r += 512) {
            s0 += job_emb[r * H + col];
            s1 += job_emb[(r + 128) * H + col];
            s2 += job_emb[(r + 256) * H + col];
            s3 += job_emb[(r + 384) * H + col];
        }
        for (; r < NJ; r += 128) s0 += job_emb[r * H + col];
        d_partJ[pb * H + col] = s0 + s1 + s2 + s3;
    } else if (bx == 224) {
        if (tid >= 128) return;
        const int col = tid;
        float s0 = 0.f, s1 = 0.f, s2 = 0.f, s3 = 0.f;
        int r = 0;
        for (; r + 3 < NM; r += 4) {
            s0 += machine_emb[r * H + col];
            s1 += machine_emb[(r + 1) * H + col];
            s2 += machine_emb[(r + 2) * H + col];
            s3 += machine_emb[(r + 3) * H + col];
        }
        for (; r < NM; r++) s0 += machine_emb[r * H + col];
        d_partM[col] = s0 + s1 + s2 + s3;
    } else if (bx < 233) {
        if (tid >= 128) return;
        const int col = tid;
        const int sb = bx - 225;                // 0..7
        float s0 = 0.f, s1 = 0.f, s2 = 0.f, s3 = 0.f;
        int r = sb;
        for (; r + 24 < NS; r += 32) {
            s0 += setup_emb[r * H + col];
            s1 += setup_emb[(r + 8) * H + col];
            s2 += setup_emb[(r + 16) * H + col];
            s3 += setup_emb[(r + 24) * H + col];
        }
        for (; r < NS; r += 8) s0 += setup_emb[r * H + col];
        d_partS[sb * H + col] = s0 + s1 + s2 + s3;
    } else {
        // convert 20 rows of job_emb to fp16
        const int r0 = (bx - 233) * 20;
        const int base4 = r0 * 32;              // float4 index
        #pragma unroll
        for (int it = 0; it < 3; it++) {
            const int i = tid + it * 256;       // 0..639
            if (i < 640) {
                const float4 f = ((const float4*)job_emb)[base4 + i];
                const __half2 h0 = __floats2half2_rn(f.x, f.y);
                const __half2 h1 = __floats2half2_rn(f.z, f.w);
                uint2 u;
                u.x = *(const uint32_t*)&h0;
                u.y = *(const uint32_t*)&h1;
                ((uint2*)d_jemb16)[base4 + i] = u;
            }
        }
    }
}

// ===========================================================================
// k_proj: 29 blocks x 512 (unchanged from R10).
// ===========================================================================
#define PRJ_A   0
#define PRJ_W   (128 * PJB)              // 34816
#define PRJ_SMEM (PRJ_W + MH * PJB)      // 104448

__global__ __launch_bounds__(512, 1)
void k_proj(const float* __restrict__ machine_emb,
            const float* __restrict__ gf,
            const float* __restrict__ Wg,
            const float* __restrict__ bg,
            const float* __restrict__ aW1,
            const float* __restrict__ ab1)
{
    extern __shared__ char smem[];
    const int tid  = threadIdx.x;
    const int lane = tid & 31;
    const int warp = tid >> 5;
    const int bx   = blockIdx.x;

    if (bx >= 16) {
        float* fs = (float*)smem;
        float* s_sa  = fs;             // [128]
        float* s_ge  = fs + 128;       // [128]
        float* s_src = fs + 256;       // [4*128]
        const int q = bx - 16;         // 0..12
        const int r0 = q * 4;

        if (tid < 128) {
            float t = 0.f;
            #pragma unroll
            for (int g = 0; g < 8; g++) t += d_partS[g * H + tid];
            s_sa[tid] = t * (1.0f / NS);
        } else if (tid < 256) {
            const int c = tid - 128;
            float a = bg[c];
            #pragma unroll
            for (int g = 0; g < G; g++) a += gf[g] * Wg[g * H + c];
            s_ge[c] = relu(a);
        }
        {
            const int r = tid >> 7, k = tid & 127;
            const int row = r0 + r;
            s_src[tid] = (row < NM) ? machine_emb[row * H + k] : 0.f;
        }
        __syncthreads();

        if (tid < 256) {
            const int col = tid;
            float cv = ab1[col];
            #pragma unroll 8
            for (int k = 0; k < 128; k++) {
                cv += s_sa[k] * aW1[(2 * H + k) * MH + col];
                cv += s_ge[k] * aW1[(3 * H + k) * MH + col];
            }
            const float* __restrict__ W = aW1 + H * MH;
            float a0 = 0.f, a1 = 0.f, a2 = 0.f, a3 = 0.f;
            #pragma unroll 8
            for (int k = 0; k < H; k++) {
                const float w = W[k * MH + col];
                a0 += s_src[k] * w;
                a1 += s_src[128 + k] * w;
                a2 += s_src[256 + k] * w;
                a3 += s_src[384 + k] * w;
            }
            if (r0 + 0 < NM) d_Pm16[(r0 + 0) * PADK + col] = __float2half_rn(a0 + cv);
            if (r0 + 1 < NM) d_Pm16[(r0 + 1) * PADK + col] = __float2half_rn(a1 + cv);
            if (r0 + 2 < NM) d_Pm16[(r0 + 2) * PADK + col] = __float2half_rn(a2 + cv);
            if (r0 + 3 < NM) d_Pm16[(r0 + 3) * PADK + col] = __float2half_rn(a3 + cv);
        }
        return;
    }

    // ---------------- Pj GEMM blocks ----------------
    const int j0 = bx * 128;
    const uint32_t sb = smem_u32(smem);

    #pragma unroll
    for (int it = 0; it < 4; it++) {
        const int idx = tid + it * 512;
        const int row = idx >> 4, qd = idx & 15;
        const int jr = j0 + row;
        uint4 v = make_uint4(0u, 0u, 0u, 0u);
        if (jr < NJ) v = ((const uint4*)(d_jemb16 + jr * H))[qd];
        *(uint4*)(smem + PRJ_A + row * PJB + qd * 16) = v;
    }
    #pragma unroll
    for (int it = 0; it < 9; it++) {
        const int idx = tid + it * 512;
        if (idx < 4352)
            ((uint4*)(smem + PRJ_W))[idx] = ((const uint4*)d_W1t16)[idx];
    }
    __syncthreads();

    const int wm = warp >> 2, wn = warp & 3;
    const int r4 = lane >> 2, kq = (lane & 3) * 2;

    const uint32_t aBase = sb + PRJ_A
        + (uint32_t)(wm * 32 + (lane & 15)) * PJB + ((lane >> 4) << 4);
    uint32_t bBase[4];
    #pragma unroll
    for (int ntp = 0; ntp < 4; ntp++)
        bBase[ntp] = sb + PRJ_W
            + (uint32_t)(wn * 64 + ntp * 16 + ((lane >> 4) << 3) + (lane & 7)) * PJB
            + (((lane >> 3) & 1) << 4);

    float acc[2][8][4];
    #pragma unroll
    for (int mt = 0; mt < 2; mt++)
        #pragma unroll
        for (int nt = 0; nt < 8; nt++)
            #pragma unroll
            for (int c = 0; c < 4; c++) acc[mt][nt][c] = 0.f;

    #pragma unroll
    for (int ks = 0; ks < 8; ks++) {
        const uint32_t kB = ks * 32;
        uint32_t a[2][4];
        #pragma unroll
        for (int mt = 0; mt < 2; mt++)
            ldm_x4(a[mt][0], a[mt][1], a[mt][2], a[mt][3],
                   aBase + mt * (16 * PJB) + kB);
        #pragma unroll
        for (int ntp = 0; ntp < 4; ntp++) {
            uint32_t b0, b1, b2, b3;
            ldm_x4(b0, b1, b2, b3, bBase[ntp] + kB);
            HMMA(acc[0][ntp * 2],     a[0][0], a[0][1], a[0][2], a[0][3], b0, b1);
            HMMA(acc[0][ntp * 2 + 1], a[0][0], a[0][1], a[0][2], a[0][3], b2, b3);
            HMMA(acc[1][ntp * 2],     a[1][0], a[1][1], a[1][2], a[1][3], b0, b1);
            HMMA(acc[1][ntp * 2 + 1], a[1][0], a[1][1], a[1][2], a[1][3], b2, b3);
        }
    }

    #pragma unroll
    for (int mt = 0; mt < 2; mt++)
        #pragma unroll
        for (int nt = 0; nt < 8; nt++) {
            const int col0 = wn * 64 + nt * 8 + kq;
            #pragma unroll
            for (int g = 0; g < 2; g++) {
                const int row = wm * 32 + mt * 16 + g * 8 + r4;
                const __half2 h = __floats2half2_rn(acc[mt][nt][g * 2],
                                                    acc[mt][nt][g * 2 + 1]);
                *(uint32_t*)(d_Pj16 + (size_t)(j0 + row) * PADK + col0) =
                    *(const uint32_t*)&h;
            }
        }
}

// ===========================================================================
// k3: 148 persistent blocks x 1024 threads (32 warps, 4m x 8n).
// Occupancy experiment: 50% occ vs 25%. Per-warp tile 32 rows x 32 cols.
// ===========================================================================
#define OFF_B   0
#define OFF_PJ  135168
#define OFF_PM  202752
#define OFF_B2  203776
#define OFF_W3  204800
#define OFF_RED 205824
#define K3_SMEM 209920      // OFF_RED + 128*8*4

__global__ __launch_bounds__(1024, 1)
void k3_mma(const float* __restrict__ ab2,
            const float* __restrict__ aW3,
            const float* __restrict__ ab3,
            const float* __restrict__ gf,
            const float* __restrict__ Wg,
            const float* __restrict__ bg,
            const float* __restrict__ cW1, const float* __restrict__ cb1,
            const float* __restrict__ cW2, const float* __restrict__ cb2,
            const float* __restrict__ cW3, const float* __restrict__ cb3,
            float* __restrict__ out, float* __restrict__ out_value)
{
    extern __shared__ char smem[];
    const int tid  = threadIdx.x;
    const int lane = tid & 31;
    const int warp = tid >> 5;
    const int b    = blockIdx.x;

    if (b == 0) {
        float* cs = (float*)smem;
        if (tid < 128) {
            float t = 0.f;
            #pragma unroll
            for (int g = 0; g < 128; g++) t += d_partJ[g * H + tid];
            cs[tid] = t * (1.0f / NJ);
            cs[H + tid] = d_partM[tid] * (1.0f / NM);
            float u = 0.f;
            #pragma unroll
            for (int g = 0; g < 8; g++) u += d_partS[g * H + tid];
            cs[2 * H + tid] = u * (1.0f / NS);
            float a = bg[tid];
            #pragma unroll
            for (int g = 0; g < G; g++) a += gf[g] * Wg[g * H + tid];
            cs[3 * H + tid] = relu(a);
        }
        __syncthreads();
        if (tid < 512) {
            const int col = tid >> 1, half = tid & 1;
            float s = 0.f;
            const int kb = half * 256;
            #pragma unroll 16
            for (int k = 0; k < 256; k++)
                s += cs[kb + k] * cW1[(kb + k) * MH + col];
            s += __shfl_xor_sync(0xffffffffu, s, 1);
            if (half == 0) cs[512 + col] = relu(s + cb1[col]);
        }
        __syncthreads();
        if (tid < 512) {
            const int col = tid >> 1, half = tid & 1;
            float s = 0.f;
            const int kb = half * 128;
            #pragma unroll 16
            for (int k = 0; k < 128; k++)
                s += cs[512 + kb + k] * cW2[(kb + k) * MH + col];
            s += __shfl_xor_sync(0xffffffffu, s, 1);
            if (half == 0) cs[768 + col] = relu(s + cb2[col]) * cW3[col];
        }
        __syncthreads();
        {
            float v = (tid < 256) ? cs[768 + tid] : 0.f;
            #pragma unroll
            for (int off = 16; off; off >>= 1) v += __shfl_xor_sync(0xffffffffu, v, off);
            __syncthreads();
            if (lane == 0) cs[warp] = v;
            __syncthreads();
            if (tid == 0) {
                float t = cb3[0];
                #pragma unroll
                for (int w = 0; w < 32; w++) t += cs[w];
                *out_value = t;
            }
        }
        __syncthreads();
    }

    int p0, p1;
    if (b == 0) { p0 = 0; p1 = 3; }
    else {
        p0 = 3 + (int)(((long long)(b - 1) * 797) / 147);
        p1 = 3 + (int)(((long long)b * 797) / 147);
    }

    float* s_b2  = (float*)(smem + OFF_B2);
    float* s_w3  = (float*)(smem + OFF_W3);
    float* s_red = (float*)(smem + OFF_RED);
    const uint32_t sb = smem_u32(smem);

    {
        const uint4* src = (const uint4*)d_B16;
        uint4* dst = (uint4*)(smem + OFF_B);
        #pragma unroll
        for (int i = 0; i < 9; i++) {
            const int idx = tid + i * 1024;
            if (idx < 8448) dst[idx] = src[idx];
        }
        if (tid < 256) s_b2[tid] = ab2[tid];
        else if (tid < 512) s_w3[tid - 256] = aW3[tid - 256];
    }

    const int wm = warp >> 3;            // 0..3 : 32-row band
    const int wn = warp & 7;             // 0..7 : 32-col band
    const int r4 = lane >> 2;
    const int kq = (lane & 3) * 2;
    const float bias3 = ab3[0];

    const uint32_t aBase = sb + OFF_PJ
        + (uint32_t)(wm * 32 + (lane & 15)) * ROWB + ((lane >> 4) << 4);
    uint32_t bBase[2];
    #pragma unroll
    for (int ntp = 0; ntp < 2; ntp++)
        bBase[ntp] = sb + OFF_B
            + (uint32_t)(wn * 32 + ntp * 16 + ((lane >> 4) << 3) + (lane & 7)) * ROWB
            + (((lane >> 3) & 1) << 4);
    const uint32_t pmBase = sb + OFF_PM + kq * 2;

    int cur_jt = -1;
    for (int p = p0; p < p1; p++) {
        const int jt = p / NM;
        const int m  = p - jt * NM;
        const int j0 = jt * 128;

        __syncthreads();
        if (jt != cur_jt) {
            const uint4* srcp = (const uint4*)((const char*)d_Pj16 + (size_t)j0 * ROWB);
            uint4* dstp = (uint4*)(smem + OFF_PJ);
            #pragma unroll
            for (int i = 0; i < 5; i++) {
                const int idx = tid + i * 1024;
                if (idx < 4224) dstp[idx] = srcp[idx];
            }
            cur_jt = jt;
        }
        if (tid < 128)
            ((uint32_t*)(smem + OFF_PM))[tid] =
                ((const uint32_t*)((const char*)d_Pm16 + (size_t)m * ROWB))[tid];
        __syncthreads();

        float acc[2][4][4];
        #pragma unroll
        for (int mt = 0; mt < 2; mt++)
            #pragma unroll
            for (int nt = 0; nt < 4; nt++)
                #pragma unroll
                for (int c = 0; c < 4; c++) acc[mt][nt][c] = 0.f;

        #pragma unroll 4
        for (int ks = 0; ks < 16; ks++) {
            const uint32_t kB = ks * 32;
            uint32_t pm0, pm1;
            asm volatile("ld.shared.b32 %0, [%1];" : "=r"(pm0) : "r"(pmBase + kB));
            asm volatile("ld.shared.b32 %0, [%1];" : "=r"(pm1) : "r"(pmBase + kB + 16));

            uint32_t a[2][4];
            #pragma unroll
            for (int mt = 0; mt < 2; mt++) {
                ldm_x4(a[mt][0], a[mt][1], a[mt][2], a[mt][3],
                       aBase + mt * (16 * ROWB) + kB);
                a[mt][0] = addrelu2(a[mt][0], pm0);
                a[mt][1] = addrelu2(a[mt][1], pm0);
                a[mt][2] = addrelu2(a[mt][2], pm1);
                a[mt][3] = addrelu2(a[mt][3], pm1);
            }
            #pragma unroll
            for (int ntp = 0; ntp < 2; ntp++) {
                uint32_t b0, b1, b2, b3;
                ldm_x4(b0, b1, b2, b3, bBase[ntp] + kB);
                HMMA(acc[0][ntp * 2],     a[0][0], a[0][1], a[0][2], a[0][3], b0, b1);
                HMMA(acc[0][ntp * 2 + 1], a[0][0], a[0][1], a[0][2], a[0][3], b2, b3);
                HMMA(acc[1][ntp * 2],     a[1][0], a[1][1], a[1][2], a[1][3], b0, b1);
                HMMA(acc[1][ntp * 2 + 1], a[1][0], a[1][1], a[1][2], a[1][3], b2, b3);
            }
        }

        float part[2][2] = {{0.f, 0.f}, {0.f, 0.f}};
        #pragma unroll
        for (int nt = 0; nt < 4; nt++) {
            const int col0 = wn * 32 + nt * 8 + kq;
            const float b2a = s_b2[col0],     w3a = s_w3[col0];
            const float b2b = s_b2[col0 + 1], w3b = s_w3[col0 + 1];
            #pragma unroll
            for (int mt = 0; mt < 2; mt++) {
                part[mt][0] += relu(acc[mt][nt][0] + b2a) * w3a
                             + relu(acc[mt][nt][1] + b2b) * w3b;
                part[mt][1] += relu(acc[mt][nt][2] + b2a) * w3a
                             + relu(acc[mt][nt][3] + b2b) * w3b;
            }
        }
        #pragma unroll
        for (int mt = 0; mt < 2; mt++)
            #pragma unroll
            for (int g = 0; g < 2; g++) {
                part[mt][g] += __shfl_xor_sync(0xffffffffu, part[mt][g], 1);
                part[mt][g] += __shfl_xor_sync(0xffffffffu, part[mt][g], 2);
            }
        if ((lane & 3) == 0) {
            #pragma unroll
            for (int mt = 0; mt < 2; mt++)
                #pragma unroll
                for (int g = 0; g < 2; g++) {
                    const int rl = wm * 32 + mt * 16 + g * 8 + r4;
                    s_red[rl * 8 + wn] = part[mt][g];
                }
        }
        __syncthreads();
        if (tid < 128) {
            const int j = j0 + tid;
            if (j < NJ) {
                float v = bias3;
                #pragma unroll
                for (int w = 0; w < 8; w++) v += s_red[tid * 8 + w];
                out[j * NM + m] = v;
            }
        }
    }
}

// ===========================================================================
extern "C" void kernel_launch(void* const* d_in, const int* in_sizes, int n_in,
                              void* d_out, int out_size)
{
    const float* job_emb     = (const float*)d_in[0];
    const float* machine_emb = (const float*)d_in[1];
    const float* setup_emb   = (const float*)d_in[2];
    const float* gf          = (const float*)d_in[3];
    const float* Wg          = (const float*)d_in[4];
    const float* bg          = (const float*)d_in[5];
    const float* aW1         = (const float*)d_in[6];
    const float* ab1         = (const float*)d_in[7];
    const float* aW2         = (const float*)d_in[8];
    const float* ab2         = (const float*)d_in[9];
    const float* aW3         = (const float*)d_in[10];
    const float* ab3         = (const float*)d_in[11];
    const float* cW1         = (const float*)d_in[12];
    const float* cb1         = (const float*)d_in[13];
    const float* cW2         = (const float*)d_in[14];
    const float* cb2         = (const float*)d_in[15];
    const float* cW3         = (const float*)d_in[16];
    const float* cb3         = (const float*)d_in[17];

    float* out = (float*)d_out;
    float* out_value = out + (out_size - 1);

    cudaFuncSetAttribute(k_proj, cudaFuncAttributeMaxDynamicSharedMemorySize, PRJ_SMEM);
    cudaFuncSetAttribute(k3_mma, cudaFuncAttributeMaxDynamicSharedMemorySize, K3_SMEM);

    k_prep<<<333, 256>>>(job_emb, machine_emb, setup_emb, aW1, aW2);
    k_proj<<<29, 512, PRJ_SMEM>>>(machine_emb, gf, Wg, bg, aW1, ab1);
    k3_mma<<<148, 1024, K3_SMEM>>>(ab2, aW3, ab3, gf, Wg, bg,
                                   cW1, cb1, cW2, cb2, cW3, cb3,
                                   out, out_value);
}

// round 13
// speedup vs baseline: 1.1022x; 1.1022x over previous
#include <cuda_runtime.h>
#include <cuda_fp16.h>
#include <cstdint>

#define H   128
#define MH  256
#define NJ  2000
#define NJP 2048
#define NM  50
#define NS  200
#define G   8

#define PADK  264                 // padded row length for Pj/Pm/B (halves)
#define ROWB  528                 // bytes per padded row
#define PJK   136                 // padded row length for W1t / A-tiles (halves)
#define PJB   272                 // bytes

// ---------------- device scratch ----------------
__device__ __half d_Pj16[NJP * PADK];   // job projections, fp16
__device__ __half d_Pm16[NM * PADK];    // machine proj + cvec, fp16
__device__ __half d_B16[MH * PADK];     // aW2^T [n][k] fp16
__device__ __half d_W1t16[MH * PJK];    // aW1[0:128]^T [n][k] fp16
__device__ float  d_partJ[128 * H];
__device__ float  d_partM[H];
__device__ float  d_partS[8 * H];

__device__ __forceinline__ float relu(float x) { return fmaxf(x, 0.f); }

__device__ __forceinline__ uint32_t smem_u32(const void* p) {
    uint32_t a;
    asm("{ .reg .u64 t; cvta.to.shared.u64 t, %1; cvt.u32.u64 %0, t; }" : "=r"(a) : "l"(p));
    return a;
}
__device__ __forceinline__ void ldm_x4(uint32_t& r0, uint32_t& r1, uint32_t& r2,
                                       uint32_t& r3, uint32_t addr) {
    asm volatile("ldmatrix.sync.aligned.m8n8.x4.shared.b16 {%0,%1,%2,%3}, [%4];"
                 : "=r"(r0), "=r"(r1), "=r"(r2), "=r"(r3) : "r"(addr));
}
__device__ __forceinline__ uint32_t addrelu2(uint32_t a, uint32_t pm) {
    const __half2 z = __float2half2_rn(0.f);
    __half2 x = __hadd2(*(__half2*)&a, *(__half2*)&pm);
    x = __hmax2(x, z);
    return *(uint32_t*)&x;
}
#define HMMA(acc, A0, A1, A2, A3, B0, B1)                                   \
    asm volatile(                                                            \
        "mma.sync.aligned.m16n8k16.row.col.f32.f16.f16.f32 "                \
        "{%0,%1,%2,%3}, {%4,%5,%6,%7}, {%8,%9}, {%0,%1,%2,%3};"             \
        : "+f"(acc[0]), "+f"(acc[1]), "+f"(acc[2]), "+f"(acc[3])            \
        : "r"(A0), "r"(A1), "r"(A2), "r"(A3), "r"(B0), "r"(B1))

// ===========================================================================
// k_prep: 233 blocks x 256.
//   0..31   : transpose aW1[0:128] -> d_W1t16
//   32..95  : transpose aW2       -> d_B16
//   96..223 : job partial sums (128 blocks, ~4 DRAM rounds each)
//   224     : machine partial
//   225..232: setup partials (8)
// ===========================================================================
__global__ __launch_bounds__(256)
void k_prep(const float* __restrict__ job_emb,
            const float* __restrict__ machine_emb,
            const float* __restrict__ setup_emb,
            const float* __restrict__ aW1,
            const float* __restrict__ aW2)
{
    __shared__ float buf[32 * 33];
    const int bx = blockIdx.x;
    const int tid = threadIdx.x;

    if (bx < 32) {
        float (*tt)[33] = (float(*)[33])buf;
        const int t = bx;
        const int k0 = (t >> 3) * 32, n0 = (t & 7) * 32;
        const int r = tid >> 5, c = tid & 31;
        #pragma unroll
        for (int i = 0; i < 4; i++)
            tt[r + i * 8][c] = aW1[(k0 + r + i * 8) * MH + n0 + c];
        __syncthreads();
        #pragma unroll
        for (int i = 0; i < 4; i++)
            d_W1t16[(n0 + r + i * 8) * PJK + k0 + c] = __float2half_rn(tt[c][r + i * 8]);
    } else if (bx < 96) {
        float (*tt)[33] = (float(*)[33])buf;
        const int t = bx - 32;
        const int k0 = (t >> 3) * 32, n0 = (t & 7) * 32;
        const int r = tid >> 5, c = tid & 31;
        #pragma unroll
        for (int i = 0; i < 4; i++)
            tt[r + i * 8][c] = aW2[(k0 + r + i * 8) * MH + n0 + c];
        __syncthreads();
        #pragma unroll
        for (int i = 0; i < 4; i++)
            d_B16[(n0 + r + i * 8) * PADK + k0 + c] = __float2half_rn(tt[c][r + i * 8]);
    } else if (bx < 224) {
        if (tid >= 128) return;
        const int col = tid;
        const int pb = bx - 96;                 // 0..127
        float s0 = 0.f, s1 = 0.f, s2 = 0.f, s3 = 0.f;
        int r = pb;
        for (; r + 384 < NJ; r += 512) {
            s0 += job_emb[r * H + col];
            s1 += job_emb[(r + 128) * H + col];
            s2 += job_emb[(r + 256) * H + col];
            s3 += job_emb[(r + 384) * H + col];
        }
        for (; r < NJ; r += 128) s0 += job_emb[r * H + col];
        d_partJ[pb * H + col] = s0 + s1 + s2 + s3;
    } else if (bx == 224) {
        if (tid >= 128) return;
        const int col = tid;
        float s0 = 0.f, s1 = 0.f, s2 = 0.f, s3 = 0.f;
        int r = 0;
        for (; r + 3 < NM; r += 4) {
            s0 += machine_emb[r * H + col];
            s1 += machine_emb[(r + 1) * H + col];
            s2 += machine_emb[(r + 2) * H + col];
            s3 += machine_emb[(r + 3) * H + col];
        }
        for (; r < NM; r++) s0 += machine_emb[r * H + col];
        d_partM[col] = s0 + s1 + s2 + s3;
    } else {
        if (tid >= 128) return;
        const int col = tid;
        const int sb = bx - 225;                // 0..7
        float s0 = 0.f, s1 = 0.f, s2 = 0.f, s3 = 0.f;
        int r = sb;
        for (; r + 24 < NS; r += 32) {
            s0 += setup_emb[r * H + col];
            s1 += setup_emb[(r + 8) * H + col];
            s2 += setup_emb[(r + 16) * H + col];
            s3 += setup_emb[(r + 24) * H + col];
        }
        for (; r < NS; r += 8) s0 += setup_emb[r * H + col];
        d_partS[sb * H + col] = s0 + s1 + s2 + s3;
    }
}

// ===========================================================================
// k_proj: 29 blocks x 512.
//   0..15 : Pj j-tile GEMM via HMMA; A tile converted fp32->fp16 in-flight
//   16..28: c_vec + 4 machine rows each -> d_Pm16
// ===========================================================================
#define PRJ_A   0
#define PRJ_W   (128 * PJB)              // 34816
#define PRJ_SMEM (PRJ_W + MH * PJB)      // 104448

__global__ __launch_bounds__(512, 1)
void k_proj(const float* __restrict__ job_emb,
            const float* __restrict__ machine_emb,
            const float* __restrict__ gf,
            const float* __restrict__ Wg,
            const float* __restrict__ bg,
            const float* __restrict__ aW1,
            const float* __restrict__ ab1)
{
    extern __shared__ char smem[];
    const int tid  = threadIdx.x;
    const int lane = tid & 31;
    const int warp = tid >> 5;
    const int bx   = blockIdx.x;

    if (bx >= 16) {
        float* fs = (float*)smem;
        float* s_sa  = fs;             // [128]
        float* s_ge  = fs + 128;       // [128]
        float* s_src = fs + 256;       // [4*128]
        const int q = bx - 16;         // 0..12
        const int r0 = q * 4;

        if (tid < 128) {
            float t = 0.f;
            #pragma unroll
            for (int g = 0; g < 8; g++) t += d_partS[g * H + tid];
            s_sa[tid] = t * (1.0f / NS);
        } else if (tid < 256) {
            const int c = tid - 128;
            float a = bg[c];
            #pragma unroll
            for (int g = 0; g < G; g++) a += gf[g] * Wg[g * H + c];
            s_ge[c] = relu(a);
        }
        {
            const int r = tid >> 7, k = tid & 127;
            const int row = r0 + r;
            s_src[tid] = (row < NM) ? machine_emb[row * H + k] : 0.f;
        }
        __syncthreads();

        if (tid < 256) {
            const int col = tid;
            float cv = ab1[col];
            #pragma unroll 8
            for (int k = 0; k < 128; k++) {
                cv += s_sa[k] * aW1[(2 * H + k) * MH + col];
                cv += s_ge[k] * aW1[(3 * H + k) * MH + col];
            }
            const float* __restrict__ W = aW1 + H * MH;
            float a0 = 0.f, a1 = 0.f, a2 = 0.f, a3 = 0.f;
            #pragma unroll 8
            for (int k = 0; k < H; k++) {
                const float w = W[k * MH + col];
                a0 += s_src[k] * w;
                a1 += s_src[128 + k] * w;
                a2 += s_src[256 + k] * w;
                a3 += s_src[384 + k] * w;
            }
            if (r0 + 0 < NM) d_Pm16[(r0 + 0) * PADK + col] = __float2half_rn(a0 + cv);
            if (r0 + 1 < NM) d_Pm16[(r0 + 1) * PADK + col] = __float2half_rn(a1 + cv);
            if (r0 + 2 < NM) d_Pm16[(r0 + 2) * PADK + col] = __float2half_rn(a2 + cv);
            if (r0 + 3 < NM) d_Pm16[(r0 + 3) * PADK + col] = __float2half_rn(a3 + cv);
        }
        return;
    }

    // ---------------- Pj GEMM blocks ----------------
    const int j0 = bx * 128;
    const uint32_t sb = smem_u32(smem);

    // fill A tile from fp32 job_emb, converting in-flight (128 rows x 32 float4)
    #pragma unroll
    for (int it = 0; it < 8; it++) {
        const int idx = tid + it * 512;           // 0..4095
        const int row = idx >> 5, q4 = idx & 31;
        const int jr = j0 + row;
        uint2 u = make_uint2(0u, 0u);
        if (jr < NJ) {
            const float4 f = ((const float4*)(job_emb + jr * H))[q4];
            const __half2 h0 = __floats2half2_rn(f.x, f.y);
            const __half2 h1 = __floats2half2_rn(f.z, f.w);
            u.x = *(const uint32_t*)&h0;
            u.y = *(const uint32_t*)&h1;
        }
        *(uint2*)(smem + PRJ_A + row * PJB + q4 * 8) = u;
    }
    #pragma unroll
    for (int it = 0; it < 9; it++) {
        const int idx = tid + it * 512;
        if (idx < 4352)
            ((uint4*)(smem + PRJ_W))[idx] = ((const uint4*)d_W1t16)[idx];
    }
    __syncthreads();

    const int wm = warp >> 2, wn = warp & 3;
    const int r4 = lane >> 2, kq = (lane & 3) * 2;

    const uint32_t aBase = sb + PRJ_A
        + (uint32_t)(wm * 32 + (lane & 15)) * PJB + ((lane >> 4) << 4);
    uint32_t bBase[4];
    #pragma unroll
    for (int ntp = 0; ntp < 4; ntp++)
        bBase[ntp] = sb + PRJ_W
            + (uint32_t)(wn * 64 + ntp * 16 + ((lane >> 4) << 3) + (lane & 7)) * PJB
            + (((lane >> 3) & 1) << 4);

    float acc[2][8][4];
    #pragma unroll
    for (int mt = 0; mt < 2; mt++)
        #pragma unroll
        for (int nt = 0; nt < 8; nt++)
            #pragma unroll
            for (int c = 0; c < 4; c++) acc[mt][nt][c] = 0.f;

    #pragma unroll
    for (int ks = 0; ks < 8; ks++) {
        const uint32_t kB = ks * 32;
        uint32_t a[2][4];
        #pragma unroll
        for (int mt = 0; mt < 2; mt++)
            ldm_x4(a[mt][0], a[mt][1], a[mt][2], a[mt][3],
                   aBase + mt * (16 * PJB) + kB);
        #pragma unroll
        for (int ntp = 0; ntp < 4; ntp++) {
            uint32_t b0, b1, b2, b3;
            ldm_x4(b0, b1, b2, b3, bBase[ntp] + kB);
            HMMA(acc[0][ntp * 2],     a[0][0], a[0][1], a[0][2], a[0][3], b0, b1);
            HMMA(acc[0][ntp * 2 + 1], a[0][0], a[0][1], a[0][2], a[0][3], b2, b3);
            HMMA(acc[1][ntp * 2],     a[1][0], a[1][1], a[1][2], a[1][3], b0, b1);
            HMMA(acc[1][ntp * 2 + 1], a[1][0], a[1][1], a[1][2], a[1][3], b2, b3);
        }
    }

    #pragma unroll
    for (int mt = 0; mt < 2; mt++)
        #pragma unroll
        for (int nt = 0; nt < 8; nt++) {
            const int col0 = wn * 64 + nt * 8 + kq;
            #pragma unroll
            for (int g = 0; g < 2; g++) {
                const int row = wm * 32 + mt * 16 + g * 8 + r4;
                const __half2 h = __floats2half2_rn(acc[mt][nt][g * 2],
                                                    acc[mt][nt][g * 2 + 1]);
                *(uint32_t*)(d_Pj16 + (size_t)(j0 + row) * PADK + col0) =
                    *(const uint32_t*)&h;
            }
        }
}

// ===========================================================================
// k3: 148 persistent blocks x 512 threads (R10-proven body, unroll 4).
// ===========================================================================
#define OFF_B   0
#define OFF_PJ  135168
#define OFF_PM  202752
#define OFF_B2  203776
#define OFF_W3  204800
#define OFF_RED 205824
#define K3_SMEM 207872

__global__ __launch_bounds__(512, 1)
void k3_mma(const float* __restrict__ ab2,
            const float* __restrict__ aW3,
            const float* __restrict__ ab3,
            const float* __restrict__ gf,
            const float* __restrict__ Wg,
            const float* __restrict__ bg,
            const float* __restrict__ cW1, const float* __restrict__ cb1,
            const float* __restrict__ cW2, const float* __restrict__ cb2,
            const float* __restrict__ cW3, const float* __restrict__ cb3,
            float* __restrict__ out, float* __restrict__ out_value)
{
    extern __shared__ char smem[];
    const int tid  = threadIdx.x;
    const int lane = tid & 31;
    const int warp = tid >> 5;
    const int b    = blockIdx.x;

    if (b == 0) {
        float* cs = (float*)smem;
        if (tid < 128) {
            float t = 0.f;
            #pragma unroll
            for (int g = 0; g < 128; g++) t += d_partJ[g * H + tid];
            cs[tid] = t * (1.0f / NJ);
            cs[H + tid] = d_partM[tid] * (1.0f / NM);
            float u = 0.f;
            #pragma unroll
            for (int g = 0; g < 8; g++) u += d_partS[g * H + tid];
            cs[2 * H + tid] = u * (1.0f / NS);
            float a = bg[tid];
            #pragma unroll
            for (int g = 0; g < G; g++) a += gf[g] * Wg[g * H + tid];
            cs[3 * H + tid] = relu(a);
        }
        __syncthreads();
        {
            const int col = tid >> 1, half = tid & 1;
            float s = 0.f;
            const int kb = half * 256;
            #pragma unroll 16
            for (int k = 0; k < 256; k++)
                s += cs[kb + k] * cW1[(kb + k) * MH + col];
            s += __shfl_xor_sync(0xffffffffu, s, 1);
            __syncthreads();
            if (half == 0) cs[512 + col] = relu(s + cb1[col]);
        }
        __syncthreads();
        {
            const int col = tid >> 1, half = tid & 1;
            float s = 0.f;
            const int kb = half * 128;
            #pragma unroll 16
            for (int k = 0; k < 128; k++)
                s += cs[512 + kb + k] * cW2[(kb + k) * MH + col];
            s += __shfl_xor_sync(0xffffffffu, s, 1);
            __syncthreads();
            if (half == 0) cs[768 + col] = relu(s + cb2[col]) * cW3[col];
        }
        __syncthreads();
        {
            float v = (tid < 256) ? cs[768 + tid] : 0.f;
            #pragma unroll
            for (int off = 16; off; off >>= 1) v += __shfl_xor_sync(0xffffffffu, v, off);
            __syncthreads();
            if (lane == 0) cs[warp] = v;
            __syncthreads();
            if (tid == 0) {
                float t = cb3[0];
                #pragma unroll
                for (int w = 0; w < 16; w++) t += cs[w];
                *out_value = t;
            }
        }
        __syncthreads();
    }

    int p0, p1;
    if (b == 0) { p0 = 0; p1 = 3; }
    else {
        p0 = 3 + (int)(((long long)(b - 1) * 797) / 147);
        p1 = 3 + (int)(((long long)b * 797) / 147);
    }

    float* s_b2  = (float*)(smem + OFF_B2);
    float* s_w3  = (float*)(smem + OFF_W3);
    float* s_red = (float*)(smem + OFF_RED);
    const uint32_t sb = smem_u32(smem);

    {
        const uint4* src = (const uint4*)d_B16;
        uint4* dst = (uint4*)(smem + OFF_B);
        #pragma unroll
        for (int i = 0; i < 17; i++) {
            const int idx = tid + i * 512;
            if (idx < 8448) dst[idx] = src[idx];
        }
        if (tid < 256) s_b2[tid] = ab2[tid];
        else           s_w3[tid - 256] = aW3[tid - 256];
    }

    const int wm = warp >> 2;
    const int wn = warp & 3;
    const int r4 = lane >> 2;
    const int kq = (lane & 3) * 2;
    const float bias3 = ab3[0];

    const uint32_t aBase = sb + OFF_PJ
        + (uint32_t)(wm * 32 + (lane & 15)) * ROWB + ((lane >> 4) << 4);
    uint32_t bBase[4];
    #pragma unroll
    for (int ntp = 0; ntp < 4; ntp++)
        bBase[ntp] = sb + OFF_B
            + (uint32_t)(wn * 64 + ntp * 16 + ((lane >> 4) << 3) + (lane & 7)) * ROWB
            + (((lane >> 3) & 1) << 4);
    const uint32_t pmBase = sb + OFF_PM + kq * 2;

    int cur_jt = -1;
    for (int p = p0; p < p1; p++) {
        const int jt = p / NM;
        const int m  = p - jt * NM;
        const int j0 = jt * 128;

        __syncthreads();
        if (jt != cur_jt) {
            const uint4* srcp = (const uint4*)((const char*)d_Pj16 + (size_t)j0 * ROWB);
            uint4* dstp = (uint4*)(smem + OFF_PJ);
            #pragma unroll
            for (int i = 0; i < 9; i++) {
                const int idx = tid + i * 512;
                if (idx < 4224) dstp[idx] = srcp[idx];
            }
            cur_jt = jt;
        }
        if (tid < 128)
            ((uint32_t*)(smem + OFF_PM))[tid] =
                ((const uint32_t*)((const char*)d_Pm16 + (size_t)m * ROWB))[tid];
        __syncthreads();

        float acc[2][8][4];
        #pragma unroll
        for (int mt = 0; mt < 2; mt++)
            #pragma unroll
            for (int nt = 0; nt < 8; nt++)
                #pragma unroll
                for (int c = 0; c < 4; c++) acc[mt][nt][c] = 0.f;

        #pragma unroll 4
        for (int ks = 0; ks < 16; ks++) {
            const uint32_t kB = ks * 32;
            uint32_t pm0, pm1;
            asm volatile("ld.shared.b32 %0, [%1];" : "=r"(pm0) : "r"(pmBase + kB));
            asm volatile("ld.shared.b32 %0, [%1];" : "=r"(pm1) : "r"(pmBase + kB + 16));

            uint32_t a[2][4];
            #pragma unroll
            for (int mt = 0; mt < 2; mt++) {
                ldm_x4(a[mt][0], a[mt][1], a[mt][2], a[mt][3],
                       aBase + mt * (16 * ROWB) + kB);
                a[mt][0] = addrelu2(a[mt][0], pm0);
                a[mt][1] = addrelu2(a[mt][1], pm0);
                a[mt][2] = addrelu2(a[mt][2], pm1);
                a[mt][3] = addrelu2(a[mt][3], pm1);
            }
            #pragma unroll
            for (int ntp = 0; ntp < 4; ntp++) {
                uint32_t b0, b1, b2, b3;
                ldm_x4(b0, b1, b2, b3, bBase[ntp] + kB);
                HMMA(acc[0][ntp * 2],     a[0][0], a[0][1], a[0][2], a[0][3], b0, b1);
                HMMA(acc[0][ntp * 2 + 1], a[0][0], a[0][1], a[0][2], a[0][3], b2, b3);
                HMMA(acc[1][ntp * 2],     a[1][0], a[1][1], a[1][2], a[1][3], b0, b1);
                HMMA(acc[1][ntp * 2 + 1], a[1][0], a[1][1], a[1][2], a[1][3], b2, b3);
            }
        }

        float part[2][2] = {{0.f, 0.f}, {0.f, 0.f}};
        #pragma unroll
        for (int nt = 0; nt < 8; nt++) {
            const int col0 = wn * 64 + nt * 8 + kq;
            const float b2a = s_b2[col0],     w3a = s_w3[col0];
            const float b2b = s_b2[col0 + 1], w3b = s_w3[col0 + 1];
            #pragma unroll
            for (int mt = 0; mt < 2; mt++) {
                part[mt][0] += relu(acc[mt][nt][0] + b2a) * w3a
                             + relu(acc[mt][nt][1] + b2b) * w3b;
                part[mt][1] += relu(acc[mt][nt][2] + b2a) * w3a
                             + relu(acc[mt][nt][3] + b2b) * w3b;
            }
        }
        #pragma unroll
        for (int mt = 0; mt < 2; mt++)
            #pragma unroll
            for (int g = 0; g < 2; g++) {
                part[mt][g] += __shfl_xor_sync(0xffffffffu, part[mt][g], 1);
                part[mt][g] += __shfl_xor_sync(0xffffffffu, part[mt][g], 2);
            }
        if ((lane & 3) == 0) {
            #pragma unroll
            for (int mt = 0; mt < 2; mt++)
                #pragma unroll
                for (int g = 0; g < 2; g++) {
                    const int rl = wm * 32 + mt * 16 + g * 8 + r4;
                    s_red[rl * 4 + wn] = part[mt][g];
                }
        }
        __syncthreads();
        if (tid < 128) {
            const int j = j0 + tid;
            if (j < NJ)
                out[j * NM + m] = s_red[tid * 4 + 0] + s_red[tid * 4 + 1]
                                + s_red[tid * 4 + 2] + s_red[tid * 4 + 3] + bias3;
        }
    }
}

// ===========================================================================
extern "C" void kernel_launch(void* const* d_in, const int* in_sizes, int n_in,
                              void* d_out, int out_size)
{
    const float* job_emb     = (const float*)d_in[0];
    const float* machine_emb = (const float*)d_in[1];
    const float* setup_emb   = (const float*)d_in[2];
    const float* gf          = (const float*)d_in[3];
    const float* Wg          = (const float*)d_in[4];
    const float* bg          = (const float*)d_in[5];
    const float* aW1         = (const float*)d_in[6];
    const float* ab1         = (const float*)d_in[7];
    const float* aW2         = (const float*)d_in[8];
    const float* ab2         = (const float*)d_in[9];
    const float* aW3         = (const float*)d_in[10];
    const float* ab3         = (const float*)d_in[11];
    const float* cW1         = (const float*)d_in[12];
    const float* cb1         = (const float*)d_in[13];
    const float* cW2         = (const float*)d_in[14];
    const float* cb2         = (const float*)d_in[15];
    const float* cW3         = (const float*)d_in[16];
    const float* cb3         = (const float*)d_in[17];

    float* out = (float*)d_out;
    float* out_value = out + (out_size - 1);

    cudaFuncSetAttribute(k_proj, cudaFuncAttributeMaxDynamicSharedMemorySize, PRJ_SMEM);
    cudaFuncSetAttribute(k3_mma, cudaFuncAttributeMaxDynamicSharedMemorySize, K3_SMEM);

    k_prep<<<233, 256>>>(job_emb, machine_emb, setup_emb, aW1, aW2);
    k_proj<<<29, 512, PRJ_SMEM>>>(job_emb, machine_emb, gf, Wg, bg, aW1, ab1);
    k3_mma<<<148, 512, K3_SMEM>>>(ab2, aW3, ab3, gf, Wg, bg,
                                  cW1, cb1, cW2, cb2, cW3, cb3,
                                  out, out_value);
}

// round 14
// speedup vs baseline: 1.1358x; 1.0305x over previous
#include <cuda_runtime.h>
#include <cuda_fp16.h>
#include <cstdint>

#define H   128
#define MH  256
#define NJ  2000
#define NJP 2048
#define NM  50
#define NS  200
#define G   8

#define PADK  264                 // padded row length for Pj/Pm/B (halves)
#define ROWB  528                 // bytes per padded row
#define PJB   272                 // A-tile row bytes (128 fp16 + pad)
#define WROWB 528                 // W1 K-major row bytes (256 fp16 + pad)

// ---------------- device scratch ----------------
__device__ __half d_Pj16[NJP * PADK];   // job projections, fp16
__device__ __half d_Pm16[NM * PADK];    // machine proj + cvec, fp16
__device__ __half d_B16[MH * PADK];     // aW2^T [n][k] fp16
__device__ float  d_partJ[128 * H];
__device__ float  d_partM[H];
__device__ float  d_partS[8 * H];

__device__ __forceinline__ float relu(float x) { return fmaxf(x, 0.f); }

__device__ __forceinline__ uint32_t smem_u32(const void* p) {
    uint32_t a;
    asm("{ .reg .u64 t; cvta.to.shared.u64 t, %1; cvt.u32.u64 %0, t; }" : "=r"(a) : "l"(p));
    return a;
}
__device__ __forceinline__ void ldm_x4(uint32_t& r0, uint32_t& r1, uint32_t& r2,
                                       uint32_t& r3, uint32_t addr) {
    asm volatile("ldmatrix.sync.aligned.m8n8.x4.shared.b16 {%0,%1,%2,%3}, [%4];"
                 : "=r"(r0), "=r"(r1), "=r"(r2), "=r"(r3) : "r"(addr));
}
__device__ __forceinline__ void ldm_x4t(uint32_t& r0, uint32_t& r1, uint32_t& r2,
                                        uint32_t& r3, uint32_t addr) {
    asm volatile("ldmatrix.sync.aligned.m8n8.x4.trans.shared.b16 {%0,%1,%2,%3}, [%4];"
                 : "=r"(r0), "=r"(r1), "=r"(r2), "=r"(r3) : "r"(addr));
}
__device__ __forceinline__ uint32_t addrelu2(uint32_t a, uint32_t pm) {
    const __half2 z = __float2half2_rn(0.f);
    __half2 x = __hadd2(*(__half2*)&a, *(__half2*)&pm);
    x = __hmax2(x, z);
    return *(uint32_t*)&x;
}
#define HMMA(acc, A0, A1, A2, A3, B0, B1)                                   \
    asm volatile(                                                            \
        "mma.sync.aligned.m16n8k16.row.col.f32.f16.f16.f32 "                \
        "{%0,%1,%2,%3}, {%4,%5,%6,%7}, {%8,%9}, {%0,%1,%2,%3};"             \
        : "+f"(acc[0]), "+f"(acc[1]), "+f"(acc[2]), "+f"(acc[3])            \
        : "r"(A0), "r"(A1), "r"(A2), "r"(A3), "r"(B0), "r"(B1))

// ===========================================================================
// k_prep: 137 blocks x 128. Partial column sums only.
//   0..127 : job partials   128 : machine   129..136 : setup
// ===========================================================================
__global__ __launch_bounds__(128)
void k_prep(const float* __restrict__ job_emb,
            const float* __restrict__ machine_emb,
            const float* __restrict__ setup_emb)
{
    const int col = threadIdx.x;
    const int bx  = blockIdx.x;
    float s0 = 0.f, s1 = 0.f, s2 = 0.f, s3 = 0.f;

    if (bx < 128) {
        int r = bx;
        for (; r + 384 < NJ; r += 512) {
            s0 += job_emb[r * H + col];
            s1 += job_emb[(r + 128) * H + col];
            s2 += job_emb[(r + 256) * H + col];
            s3 += job_emb[(r + 384) * H + col];
        }
        for (; r < NJ; r += 128) s0 += job_emb[r * H + col];
        d_partJ[bx * H + col] = s0 + s1 + s2 + s3;
    } else if (bx == 128) {
        int r = 0;
        for (; r + 3 < NM; r += 4) {
            s0 += machine_emb[r * H + col];
            s1 += machine_emb[(r + 1) * H + col];
            s2 += machine_emb[(r + 2) * H + col];
            s3 += machine_emb[(r + 3) * H + col];
        }
        for (; r < NM; r++) s0 += machine_emb[r * H + col];
        d_partM[col] = s0 + s1 + s2 + s3;
    } else {
        const int sb = bx - 129;                // 0..7
        int r = sb;
        for (; r + 24 < NS; r += 32) {
            s0 += setup_emb[r * H + col];
            s1 += setup_emb[(r + 8) * H + col];
            s2 += setup_emb[(r + 16) * H + col];
            s3 += setup_emb[(r + 24) * H + col];
        }
        for (; r < NS; r += 8) s0 += setup_emb[r * H + col];
        d_partS[sb * H + col] = s0 + s1 + s2 + s3;
    }
}

// ===========================================================================
// k_proj: 93 blocks x 512.
//   0..15 : Pj j-tile GEMM (A fp32->fp16 in-flight; W1 K-major + ldmatrix.trans)
//   16..28: c_vec + 4 machine rows each -> d_Pm16
//   29..92: aW2 transpose 32x32 tile -> d_B16 (feeds k3 only)
// ===========================================================================
#define PRJ_A   0
#define PRJ_W   (128 * PJB)                  // 34816
#define PRJ_SMEM (PRJ_W + 128 * WROWB)       // 34816 + 67584 = 102400

__global__ __launch_bounds__(512, 1)
void k_proj(const float* __restrict__ job_emb,
            const float* __restrict__ machine_emb,
            const float* __restrict__ gf,
            const float* __restrict__ Wg,
            const float* __restrict__ bg,
            const float* __restrict__ aW1,
            const float* __restrict__ ab1,
            const float* __restrict__ aW2)
{
    extern __shared__ char smem[];
    const int tid  = threadIdx.x;
    const int lane = tid & 31;
    const int warp = tid >> 5;
    const int bx   = blockIdx.x;

    if (bx >= 29) {
        // ---------------- aW2 transpose blocks (tid < 256 active) ----------
        if (tid >= 256) return;
        float (*tt)[33] = (float(*)[33])smem;
        const int t = bx - 29;
        const int k0 = (t >> 3) * 32, n0 = (t & 7) * 32;
        const int r = tid >> 5, c = tid & 31;
        #pragma unroll
        for (int i = 0; i < 4; i++)
            tt[r + i * 8][c] = aW2[(k0 + r + i * 8) * MH + n0 + c];
        __syncthreads();
        #pragma unroll
        for (int i = 0; i < 4; i++)
            d_B16[(n0 + r + i * 8) * PADK + k0 + c] = __float2half_rn(tt[c][r + i * 8]);
        return;
    }

    if (bx >= 16) {
        // ---------------- machine + cvec blocks (4 rows each) --------------
        float* fs = (float*)smem;
        float* s_sa  = fs;             // [128]
        float* s_ge  = fs + 128;       // [128]
        float* s_src = fs + 256;       // [4*128]
        const int q = bx - 16;         // 0..12
        const int r0 = q * 4;

        if (tid < 128) {
            float t = 0.f;
            #pragma unroll
            for (int g = 0; g < 8; g++) t += d_partS[g * H + tid];
            s_sa[tid] = t * (1.0f / NS);
        } else if (tid < 256) {
            const int c = tid - 128;
            float a = bg[c];
            #pragma unroll
            for (int g = 0; g < G; g++) a += gf[g] * Wg[g * H + c];
            s_ge[c] = relu(a);
        }
        {
            const int r = tid >> 7, k = tid & 127;
            const int row = r0 + r;
            s_src[tid] = (row < NM) ? machine_emb[row * H + k] : 0.f;
        }
        __syncthreads();

        if (tid < 256) {
            const int col = tid;
            float cv = ab1[col];
            #pragma unroll 8
            for (int k = 0; k < 128; k++) {
                cv += s_sa[k] * aW1[(2 * H + k) * MH + col];
                cv += s_ge[k] * aW1[(3 * H + k) * MH + col];
            }
            const float* __restrict__ W = aW1 + H * MH;
            float a0 = 0.f, a1 = 0.f, a2 = 0.f, a3 = 0.f;
            #pragma unroll 8
            for (int k = 0; k < H; k++) {
                const float w = W[k * MH + col];
                a0 += s_src[k] * w;
                a1 += s_src[128 + k] * w;
                a2 += s_src[256 + k] * w;
                a3 += s_src[384 + k] * w;
            }
            if (r0 + 0 < NM) d_Pm16[(r0 + 0) * PADK + col] = __float2half_rn(a0 + cv);
            if (r0 + 1 < NM) d_Pm16[(r0 + 1) * PADK + col] = __float2half_rn(a1 + cv);
            if (r0 + 2 < NM) d_Pm16[(r0 + 2) * PADK + col] = __float2half_rn(a2 + cv);
            if (r0 + 3 < NM) d_Pm16[(r0 + 3) * PADK + col] = __float2half_rn(a3 + cv);
        }
        return;
    }

    // ---------------- Pj GEMM blocks ----------------
    const int j0 = bx * 128;
    const uint32_t sb = smem_u32(smem);

    // A tile from fp32 job_emb, fp16 in-flight (128 rows x 32 float4)
    #pragma unroll
    for (int it = 0; it < 8; it++) {
        const int idx = tid + it * 512;           // 0..4095
        const int row = idx >> 5, q4 = idx & 31;
        const int jr = j0 + row;
        uint2 u = make_uint2(0u, 0u);
        if (jr < NJ) {
            const float4 f = ((const float4*)(job_emb + jr * H))[q4];
            const __half2 h0 = __floats2half2_rn(f.x, f.y);
            const __half2 h1 = __floats2half2_rn(f.z, f.w);
            u.x = *(const uint32_t*)&h0;
            u.y = *(const uint32_t*)&h1;
        }
        *(uint2*)(smem + PRJ_A + row * PJB + q4 * 8) = u;
    }
    // W1 rows [0,128) K-major fp16: [k][n] with WROWB-byte rows
    #pragma unroll
    for (int it = 0; it < 16; it++) {
        const int idx = tid + it * 512;           // 0..8191 float4s
        const int k = idx >> 6, n4 = idx & 63;
        const float4 f = ((const float4*)(aW1 + k * MH))[n4];
        const __half2 h0 = __floats2half2_rn(f.x, f.y);
        const __half2 h1 = __floats2half2_rn(f.z, f.w);
        uint2 u;
        u.x = *(const uint32_t*)&h0;
        u.y = *(const uint32_t*)&h1;
        *(uint2*)(smem + PRJ_W + k * WROWB + n4 * 8) = u;
    }
    __syncthreads();

    const int wm = warp >> 2, wn = warp & 3;
    const int r4 = lane >> 2, kq = (lane & 3) * 2;

    const uint32_t aBase = sb + PRJ_A
        + (uint32_t)(wm * 32 + (lane & 15)) * PJB + ((lane >> 4) << 4);
    // trans B fragments from K-major W1: row k = (lane&7) + ((lane>>3)&1)*8,
    // col n = wn*64 + ntp*16 + (lane>>4)*8
    uint32_t bBase[4];
    #pragma unroll
    for (int ntp = 0; ntp < 4; ntp++)
        bBase[ntp] = sb + PRJ_W
            + (uint32_t)((lane & 7) + ((lane >> 3) & 1) * 8) * WROWB
            + (uint32_t)(wn * 64 + ntp * 16 + ((lane >> 4) << 3)) * 2;

    float acc[2][8][4];
    #pragma unroll
    for (int mt = 0; mt < 2; mt++)
        #pragma unroll
        for (int nt = 0; nt < 8; nt++)
            #pragma unroll
            for (int c = 0; c < 4; c++) acc[mt][nt][c] = 0.f;

    #pragma unroll
    for (int ks = 0; ks < 8; ks++) {
        const uint32_t kA = ks * 32;              // A byte offset (16 fp16)
        const uint32_t kW = ks * 16 * WROWB;      // W row offset (16 k-rows)
        uint32_t a[2][4];
        #pragma unroll
        for (int mt = 0; mt < 2; mt++)
            ldm_x4(a[mt][0], a[mt][1], a[mt][2], a[mt][3],
                   aBase + mt * (16 * PJB) + kA);
        #pragma unroll
        for (int ntp = 0; ntp < 4; ntp++) {
            uint32_t b0, b1, b2, b3;
            ldm_x4t(b0, b1, b2, b3, bBase[ntp] + kW);
            HMMA(acc[0][ntp * 2],     a[0][0], a[0][1], a[0][2], a[0][3], b0, b1);
            HMMA(acc[0][ntp * 2 + 1], a[0][0], a[0][1], a[0][2], a[0][3], b2, b3);
            HMMA(acc[1][ntp * 2],     a[1][0], a[1][1], a[1][2], a[1][3], b0, b1);
            HMMA(acc[1][ntp * 2 + 1], a[1][0], a[1][1], a[1][2], a[1][3], b2, b3);
        }
    }

    #pragma unroll
    for (int mt = 0; mt < 2; mt++)
        #pragma unroll
        for (int nt = 0; nt < 8; nt++) {
            const int col0 = wn * 64 + nt * 8 + kq;
            #pragma unroll
            for (int g = 0; g < 2; g++) {
                const int row = wm * 32 + mt * 16 + g * 8 + r4;
                const __half2 h = __floats2half2_rn(acc[mt][nt][g * 2],
                                                    acc[mt][nt][g * 2 + 1]);
                *(uint32_t*)(d_Pj16 + (size_t)(j0 + row) * PADK + col0) =
                    *(const uint32_t*)&h;
            }
        }
}

// ===========================================================================
// k3: 148 persistent blocks x 512 threads (R13-proven body, unchanged).
// ===========================================================================
#define OFF_B   0
#define OFF_PJ  135168
#define OFF_PM  202752
#define OFF_B2  203776
#define OFF_W3  204800
#define OFF_RED 205824
#define K3_SMEM 207872

__global__ __launch_bounds__(512, 1)
void k3_mma(const float* __restrict__ ab2,
            const float* __restrict__ aW3,
            const float* __restrict__ ab3,
            const float* __restrict__ gf,
            const float* __restrict__ Wg,
            const float* __restrict__ bg,
            const float* __restrict__ cW1, const float* __restrict__ cb1,
            const float* __restrict__ cW2, const float* __restrict__ cb2,
            const float* __restrict__ cW3, const float* __restrict__ cb3,
            float* __restrict__ out, float* __restrict__ out_value)
{
    extern __shared__ char smem[];
    const int tid  = threadIdx.x;
    const int lane = tid & 31;
    const int warp = tid >> 5;
    const int b    = blockIdx.x;

    if (b == 0) {
        float* cs = (float*)smem;
        if (tid < 128) {
            float t = 0.f;
            #pragma unroll
            for (int g = 0; g < 128; g++) t += d_partJ[g * H + tid];
            cs[tid] = t * (1.0f / NJ);
            cs[H + tid] = d_partM[tid] * (1.0f / NM);
            float u = 0.f;
            #pragma unroll
            for (int g = 0; g < 8; g++) u += d_partS[g * H + tid];
            cs[2 * H + tid] = u * (1.0f / NS);
            float a = bg[tid];
            #pragma unroll
            for (int g = 0; g < G; g++) a += gf[g] * Wg[g * H + tid];
            cs[3 * H + tid] = relu(a);
        }
        __syncthreads();
        {
            const int col = tid >> 1, half = tid & 1;
            float s = 0.f;
            const int kb = half * 256;
            #pragma unroll 16
            for (int k = 0; k < 256; k++)
                s += cs[kb + k] * cW1[(kb + k) * MH + col];
            s += __shfl_xor_sync(0xffffffffu, s, 1);
            __syncthreads();
            if (half == 0) cs[512 + col] = relu(s + cb1[col]);
        }
        __syncthreads();
        {
            const int col = tid >> 1, half = tid & 1;
            float s = 0.f;
            const int kb = half * 128;
            #pragma unroll 16
            for (int k = 0; k < 128; k++)
                s += cs[512 + kb + k] * cW2[(kb + k) * MH + col];
            s += __shfl_xor_sync(0xffffffffu, s, 1);
            __syncthreads();
            if (half == 0) cs[768 + col] = relu(s + cb2[col]) * cW3[col];
        }
        __syncthreads();
        {
            float v = (tid < 256) ? cs[768 + tid] : 0.f;
            #pragma unroll
            for (int off = 16; off; off >>= 1) v += __shfl_xor_sync(0xffffffffu, v, off);
            __syncthreads();
            if (lane == 0) cs[warp] = v;
            __syncthreads();
            if (tid == 0) {
                float t = cb3[0];
                #pragma unroll
                for (int w = 0; w < 16; w++) t += cs[w];
                *out_value = t;
            }
        }
        __syncthreads();
    }

    int p0, p1;
    if (b == 0) { p0 = 0; p1 = 3; }
    else {
        p0 = 3 + (int)(((long long)(b - 1) * 797) / 147);
        p1 = 3 + (int)(((long long)b * 797) / 147);
    }

    float* s_b2  = (float*)(smem + OFF_B2);
    float* s_w3  = (float*)(smem + OFF_W3);
    float* s_red = (float*)(smem + OFF_RED);
    const uint32_t sb = smem_u32(smem);

    {
        const uint4* src = (const uint4*)d_B16;
        uint4* dst = (uint4*)(smem + OFF_B);
        #pragma unroll
        for (int i = 0; i < 17; i++) {
            const int idx = tid + i * 512;
            if (idx < 8448) dst[idx] = src[idx];
        }
        if (tid < 256) s_b2[tid] = ab2[tid];
        else           s_w3[tid - 256] = aW3[tid - 256];
    }

    const int wm = warp >> 2;
    const int wn = warp & 3;
    const int r4 = lane >> 2;
    const int kq = (lane & 3) * 2;
    const float bias3 = ab3[0];

    const uint32_t aBase = sb + OFF_PJ
        + (uint32_t)(wm * 32 + (lane & 15)) * ROWB + ((lane >> 4) << 4);
    uint32_t bBase[4];
    #pragma unroll
    for (int ntp = 0; ntp < 4; ntp++)
        bBase[ntp] = sb + OFF_B
            + (uint32_t)(wn * 64 + ntp * 16 + ((lane >> 4) << 3) + (lane & 7)) * ROWB
            + (((lane >> 3) & 1) << 4);
    const uint32_t pmBase = sb + OFF_PM + kq * 2;

    int cur_jt = -1;
    for (int p = p0; p < p1; p++) {
        const int jt = p / NM;
        const int m  = p - jt * NM;
        const int j0 = jt * 128;

        __syncthreads();
        if (jt != cur_jt) {
            const uint4* srcp = (const uint4*)((const char*)d_Pj16 + (size_t)j0 * ROWB);
            uint4* dstp = (uint4*)(smem + OFF_PJ);
            #pragma unroll
            for (int i = 0; i < 9; i++) {
                const int idx = tid + i * 512;
                if (idx < 4224) dstp[idx] = srcp[idx];
            }
            cur_jt = jt;
        }
        if (tid < 128)
            ((uint32_t*)(smem + OFF_PM))[tid] =
                ((const uint32_t*)((const char*)d_Pm16 + (size_t)m * ROWB))[tid];
        __syncthreads();

        float acc[2][8][4];
        #pragma unroll
        for (int mt = 0; mt < 2; mt++)
            #pragma unroll
            for (int nt = 0; nt < 8; nt++)
                #pragma unroll
                for (int c = 0; c < 4; c++) acc[mt][nt][c] = 0.f;

        #pragma unroll 4
        for (int ks = 0; ks < 16; ks++) {
            const uint32_t kB = ks * 32;
            uint32_t pm0, pm1;
            asm volatile("ld.shared.b32 %0, [%1];" : "=r"(pm0) : "r"(pmBase + kB));
            asm volatile("ld.shared.b32 %0, [%1];" : "=r"(pm1) : "r"(pmBase + kB + 16));

            uint32_t a[2][4];
            #pragma unroll
            for (int mt = 0; mt < 2; mt++) {
                ldm_x4(a[mt][0], a[mt][1], a[mt][2], a[mt][3],
                       aBase + mt * (16 * ROWB) + kB);
                a[mt][0] = addrelu2(a[mt][0], pm0);
                a[mt][1] = addrelu2(a[mt][1], pm0);
                a[mt][2] = addrelu2(a[mt][2], pm1);
                a[mt][3] = addrelu2(a[mt][3], pm1);
            }
            #pragma unroll
            for (int ntp = 0; ntp < 4; ntp++) {
                uint32_t b0, b1, b2, b3;
                ldm_x4(b0, b1, b2, b3, bBase[ntp] + kB);
                HMMA(acc[0][ntp * 2],     a[0][0], a[0][1], a[0][2], a[0][3], b0, b1);
                HMMA(acc[0][ntp * 2 + 1], a[0][0], a[0][1], a[0][2], a[0][3], b2, b3);
                HMMA(acc[1][ntp * 2],     a[1][0], a[1][1], a[1][2], a[1][3], b0, b1);
                HMMA(acc[1][ntp * 2 + 1], a[1][0], a[1][1], a[1][2], a[1][3], b2, b3);
            }
        }

        float part[2][2] = {{0.f, 0.f}, {0.f, 0.f}};
        #pragma unroll
        for (int nt = 0; nt < 8; nt++) {
            const int col0 = wn * 64 + nt * 8 + kq;
            const float b2a = s_b2[col0],     w3a = s_w3[col0];
            const float b2b = s_b2[col0 + 1], w3b = s_w3[col0 + 1];
            #pragma unroll
            for (int mt = 0; mt < 2; mt++) {
                part[mt][0] += relu(acc[mt][nt][0] + b2a) * w3a
                             + relu(acc[mt][nt][1] + b2b) * w3b;
                part[mt][1] += relu(acc[mt][nt][2] + b2a) * w3a
                             + relu(acc[mt][nt][3] + b2b) * w3b;
            }
        }
        #pragma unroll
        for (int mt = 0; mt < 2; mt++)
            #pragma unroll
            for (int g = 0; g < 2; g++) {
                part[mt][g] += __shfl_xor_sync(0xffffffffu, part[mt][g], 1);
                part[mt][g] += __shfl_xor_sync(0xffffffffu, part[mt][g], 2);
            }
        if ((lane & 3) == 0) {
            #pragma unroll
            for (int mt = 0; mt < 2; mt++)
                #pragma unroll
                for (int g = 0; g < 2; g++) {
                    const int rl = wm * 32 + mt * 16 + g * 8 + r4;
                    s_red[rl * 4 + wn] = part[mt][g];
                }
        }
        __syncthreads();
        if (tid < 128) {
            const int j = j0 + tid;
            if (j < NJ)
                out[j * NM + m] = s_red[tid * 4 + 0] + s_red[tid * 4 + 1]
                                + s_red[tid * 4 + 2] + s_red[tid * 4 + 3] + bias3;
        }
    }
}

// ===========================================================================
extern "C" void kernel_launch(void* const* d_in, const int* in_sizes, int n_in,
                              void* d_out, int out_size)
{
    const float* job_emb     = (const float*)d_in[0];
    const float* machine_emb = (const float*)d_in[1];
    const float* setup_emb   = (const float*)d_in[2];
    const float* gf          = (const float*)d_in[3];
    const float* Wg          = (const float*)d_in[4];
    const float* bg          = (const float*)d_in[5];
    const float* aW1         = (const float*)d_in[6];
    const float* ab1         = (const float*)d_in[7];
    const float* aW2         = (const float*)d_in[8];
    const float* ab2         = (const float*)d_in[9];
    const float* aW3         = (const float*)d_in[10];
    const float* ab3         = (const float*)d_in[11];
    const float* cW1         = (const float*)d_in[12];
    const float* cb1         = (const float*)d_in[13];
    const float* cW2         = (const float*)d_in[14];
    const float* cb2         = (const float*)d_in[15];
    const float* cW3         = (const float*)d_in[16];
    const float* cb3         = (const float*)d_in[17];

    float* out = (float*)d_out;
    float* out_value = out + (out_size - 1);

    cudaFuncSetAttribute(k_proj, cudaFuncAttributeMaxDynamicSharedMemorySize, PRJ_SMEM);
    cudaFuncSetAttribute(k3_mma, cudaFuncAttributeMaxDynamicSharedMemorySize, K3_SMEM);

    k_prep<<<137, 128>>>(job_emb, machine_emb, setup_emb);
    k_proj<<<93, 512, PRJ_SMEM>>>(job_emb, machine_emb, gf, Wg, bg, aW1, ab1, aW2);
    k3_mma<<<148, 512, K3_SMEM>>>(ab2, aW3, ab3, gf, Wg, bg,
                                  cW1, cb1, cW2, cb2, cW3, cb3,
                                  out, out_value);
}